// round 14
// baseline (speedup 1.0000x reference)
#include <cuda_runtime.h>
#include <cuda_fp16.h>
#include <cstdint>

#define OUT_F 11008
#define IN_F  4096
#define BATCH 32
#define GROUP 128

#define OB      128                  // M tile
#define OTILES  (OUT_F / OB)         // 86
#define KSPLIT  16
#define KRANGE  (IN_F / KSPLIT)      // 256
#define KC      64                   // k per B chunk
#define NCH     (KRANGE / KC)        // 4
#define NGRAN   (NCH * 2)            // 8 A granules (32B of k each)
#define THREADS 256
#define PWROW   (IN_F / 8)           // 512 words per output row

#define BPITCH_B 144                 // B row pitch (128B data + 16 pad)
#define SB0 0
#define SB1 4608
#define SMTOT 9216

#define DQ_MASK  0x000f000fu
#define DQ_MAGIC 0x64086408u         // fp16x2 (1032, 1032)

__device__ __half g_xh[BATCH * IN_F];    // x fp16, k-permuted

__device__ __forceinline__ uint32_t smem_u32(const void* p) {
    uint32_t a;
    asm("{ .reg .u64 t; cvta.to.shared.u64 t, %1; cvt.u32.u64 %0, t; }"
        : "=r"(a) : "l"(p));
    return a;
}
__device__ __forceinline__ void ldsm4(uint32_t& r0, uint32_t& r1, uint32_t& r2,
                                      uint32_t& r3, uint32_t addr) {
    asm volatile("ldmatrix.sync.aligned.m8n8.x4.shared.b16 {%0,%1,%2,%3}, [%4];"
                 : "=r"(r0), "=r"(r1), "=r"(r2), "=r"(r3) : "r"(addr));
}
__device__ __forceinline__ void mma_f16(float* c,
                                        uint32_t a0, uint32_t a1, uint32_t a2,
                                        uint32_t a3, uint32_t b0, uint32_t b1) {
    asm volatile(
        "mma.sync.aligned.m16n8k16.row.col.f32.f16.f16.f32 "
        "{%0,%1,%2,%3}, {%4,%5,%6,%7}, {%8,%9}, {%0,%1,%2,%3};"
        : "+f"(c[0]), "+f"(c[1]), "+f"(c[2]), "+f"(c[3])
        : "r"(a0), "r"(a1), "r"(a2), "r"(a3), "r"(b0), "r"(b1));
}
__device__ __forceinline__ void cp16(uint32_t saddr, const void* gaddr) {
    asm volatile("cp.async.cg.shared.global [%0], [%1], 16;"
                 :: "r"(saddr), "l"(gaddr) : "memory");
}
// nibbles (c, c+4) of p -> f16x2 of exact signed int4 values
__device__ __forceinline__ uint32_t dqf(uint32_t p, int sh) {
    uint32_t r = ((p >> sh) & DQ_MASK) ^ DQ_MAGIC;
    const uint32_t mg = DQ_MAGIC;
    __half2 h = __hsub2(*reinterpret_cast<__half2*>(&r),
                        *reinterpret_cast<const __half2*>(&mg));
    return *reinterpret_cast<uint32_t*>(&h);
}

// ---------------- prep: x fp16 (k-permuted) + out = bias (float4) ----------------
__global__ void prep_kernel(const float* __restrict__ x,
                            const float* __restrict__ bias,
                            float* __restrict__ out) {
    int i = blockIdx.x * blockDim.x + threadIdx.x;
    if (i < BATCH * IN_F) {
        int b = i >> 12;
        int k = i & (IN_F - 1);
        int j = k & 7;
        int kp = (k & ~7) | ((j & 3) << 1) | (j >> 2);   // nibble j -> k-slot
        g_xh[b * IN_F + kp] = __float2half_rn(x[i]);
    }
    if (i < BATCH * OUT_F / 4) {
        float4 b4 = *reinterpret_cast<const float4*>(&bias[(i * 4) % OUT_F]);
        reinterpret_cast<float4*>(out)[i] = b4;
    }
}

// ---------------- main: A-from-gmem register pipeline, B smem only ----------------
__global__ __launch_bounds__(THREADS, 4)
void wql_hmma_kernel(const int*   __restrict__ pw,
                     const float* __restrict__ scale,
                     float*       __restrict__ out) {
    extern __shared__ __align__(16) unsigned char dynsm[];
    const uint32_t smb = smem_u32(dynsm);

    const int tid   = threadIdx.x;
    const int wid   = tid >> 5;
    const int lane  = tid & 31;
    const int obase = blockIdx.x * OB;
    const int ks    = blockIdx.y;
    const int kbase = ks * KRANGE;

    const int sh = (lane & 3) * 4;           // dequant shift
    const int r0 = wid * 16 + (lane >> 2);   // A rows r0, r0+8

    const uint32_t boff = (((lane >> 4) & 1) * 8 + (lane & 7)) * BPITCH_B
                        + ((lane >> 3) & 1) * 16;

    // A granule pointers: granule g = words [4g, 4g+4) of this CTA's k-window
    const uint4* arow0 = reinterpret_cast<const uint4*>(
        &pw[(obase + r0) * PWROW + (kbase >> 3)]);
    const uint4* arow1 = reinterpret_cast<const uint4*>(
        &pw[(obase + r0 + 8) * PWROW + (kbase >> 3)]);

    // B staging role
    const int brow = tid >> 3, bseg = tid & 7;    // 32 rows x 8x16B

    float acc[4][4];
#pragma unroll
    for (int q = 0; q < 4; ++q)
#pragma unroll
        for (int j = 0; j < 4; ++j) acc[q][j] = 0.f;

    // ---- prologue: A granule 0 + B chunk 0 ----
    uint4 ga0[2], ga1[2];                     // ping-pong A granules
    ga0[0] = __ldg(&arow0[0]);
    ga1[0] = __ldg(&arow1[0]);
    {
        const __half* bsrc = &g_xh[brow * IN_F + kbase + bseg * 8];
        cp16(smb + SB0 + brow * BPITCH_B + bseg * 16, bsrc);
        asm volatile("cp.async.commit_group;" ::: "memory");
    }

    float s_prev0 = 1.f, s_prev1 = 1.f;

#pragma unroll
    for (int c = 0; c < NCH; ++c) {
        const uint32_t bb = smb + ((c & 1) ? SB1 : SB0);
        asm volatile("cp.async.wait_group 0;" ::: "memory");
        __syncthreads();

        // ---- stage B chunk c+1 into the other buffer ----
        if (c + 1 < NCH) {
            const __half* bsrc = &g_xh[brow * IN_F + kbase + (c + 1) * KC + bseg * 8];
            cp16(smb + ((c & 1) ? SB0 : SB1) + brow * BPITCH_B + bseg * 16, bsrc);
            asm volatile("cp.async.commit_group;" ::: "memory");
        }

        // ---- group boundary (every 2 chunks): rescale accumulators ----
        if ((c & 1) == 0) {
            const int gidx = ks * (KRANGE / GROUP) + (c >> 1);
            float s_cur0 = __ldg(&scale[(obase + r0) * (IN_F / GROUP) + gidx]);
            float s_cur1 = __ldg(&scale[(obase + r0 + 8) * (IN_F / GROUP) + gidx]);
            if (c) {
                float t0 = __fdividef(s_prev0, s_cur0);
                float t1 = __fdividef(s_prev1, s_cur1);
#pragma unroll
                for (int q = 0; q < 4; ++q) {
                    acc[q][0] *= t0; acc[q][1] *= t0;
                    acc[q][2] *= t1; acc[q][3] *= t1;
                }
            }
            s_prev0 = s_cur0; s_prev1 = s_cur1;
        }

        // ---- compute: 2 granules x 2 k16 steps ----
#pragma unroll
        for (int h = 0; h < 2; ++h) {
            const int g   = c * 2 + h;
            const int cur = g & 1;
            // prefetch next granule into the other reg slot
            if (g + 1 < NGRAN) {
                ga0[cur ^ 1] = __ldg(&arow0[g + 1]);
                ga1[cur ^ 1] = __ldg(&arow1[g + 1]);
            }
            const uint32_t* au = reinterpret_cast<const uint32_t*>(&ga0[cur]);
            const uint32_t* bu = reinterpret_cast<const uint32_t*>(&ga1[cur]);
#pragma unroll
            for (int s2 = 0; s2 < 2; ++s2) {
                const int s = h * 2 + s2;     // step within chunk (0..3)
                uint32_t a0 = dqf(au[2 * s2], sh);
                uint32_t a2 = dqf(au[2 * s2 + 1], sh);
                uint32_t a1 = dqf(bu[2 * s2], sh);
                uint32_t a3 = dqf(bu[2 * s2 + 1], sh);

                uint32_t b0, b1, b2, b3;
                ldsm4(b0, b1, b2, b3, bb + boff + s * 32);
                mma_f16(acc[0], a0, a1, a2, a3, b0, b1);
                mma_f16(acc[1], a0, a1, a2, a3, b2, b3);
                ldsm4(b0, b1, b2, b3, bb + boff + 16 * BPITCH_B + s * 32);
                mma_f16(acc[2], a0, a1, a2, a3, b0, b1);
                mma_f16(acc[3], a0, a1, a2, a3, b2, b3);
            }
        }
    }

    // ---- epilogue: final scale + atomics ----
    const int orow0 = obase + r0;
#pragma unroll
    for (int q = 0; q < 4; ++q) {
        const int bcol = q * 8 + (lane & 3) * 2;
        atomicAdd(&out[bcol * OUT_F + orow0],           acc[q][0] * s_prev0);
        atomicAdd(&out[(bcol + 1) * OUT_F + orow0],     acc[q][1] * s_prev0);
        atomicAdd(&out[bcol * OUT_F + orow0 + 8],       acc[q][2] * s_prev1);
        atomicAdd(&out[(bcol + 1) * OUT_F + orow0 + 8], acc[q][3] * s_prev1);
    }
}

extern "C" void kernel_launch(void* const* d_in, const int* in_sizes, int n_in,
                              void* d_out, int out_size) {
    const float* x     = (const float*)d_in[0];
    const int*   pw    = (const int*)  d_in[1];
    const float* scale = (const float*)d_in[2];
    const float* bias  = (const float*)d_in[3];
    float* out = (float*)d_out;

    static int smem_set = 0;
    if (!smem_set) {
        cudaFuncSetAttribute(wql_hmma_kernel,
                             cudaFuncAttributeMaxDynamicSharedMemorySize, SMTOT);
        smem_set = 1;
    }

    prep_kernel<<<(BATCH * IN_F + 255) / 256, 256>>>(x, bias, out);
    dim3 grid(OTILES, KSPLIT);
    wql_hmma_kernel<<<grid, THREADS, SMTOT>>>(pw, scale, out);
}